// round 5
// baseline (speedup 1.0000x reference)
#include <cuda_runtime.h>
#include <cstdint>

// ---------------------------------------------------------------------------
// Bicubic downsample 768x768 -> 384x384 (scale exactly 0.5) + constant
// 36-weight pattern tiled into the second output. Single fused launch.
//   wn  = {-9, 29, 111, 111, 29, -9} / 262
//   pat = a_p*a_q / 68644
//   gather rows/cols: clamp(2*o - 2 + tap, 0, 767)
// ---------------------------------------------------------------------------

#define IN_H   768
#define IN_W   768
#define OUT_H  384
#define OUT_W  384
#define BC     12
#define RES_ELEMS (BC * OUT_H * OUT_W)         // 1,769,472
#define KER_BYTES (4 * OUT_H * OUT_W * 36 * 4) // 84,934,656

#define BLK    128
#define TCOLS  96                              // 4 output cols per thread
#define STRIP  4
#define NSTRIPS (OUT_H / STRIP)                // 96
#define RES_THREADS (BC * NSTRIPS * TCOLS)     // 110,592
#define RES_BLOCKS  (RES_THREADS / BLK)        // 864

#define CHUNK_BYTES 9216                       // 64 pattern periods (144 B each)
#define CHUNKS_PER_FILL 16                     // 147,456 B per fill block
#define FILL_BLOCKS 576                        // 576*147456 = KER_BYTES
#define SMEM_F4 (CHUNK_BYTES / 16)             // 576 float4

#define WN0 ((float)(-9.0  / 262.0))
#define WN1 ((float)(29.0  / 262.0))
#define WN2 ((float)(111.0 / 262.0))

#define AD(p) ((p)==0 ? -9.0 : (p)==1 ? 29.0 : (p)==2 ? 111.0 : \
               (p)==3 ? 111.0 : (p)==4 ? 29.0 : -9.0)
#define PW(p,q) ((float)(AD(p) * AD(q) / 68644.0))
#define PROW(p) PW(p,0), PW(p,1), PW(p,2), PW(p,3), PW(p,4), PW(p,5)

__device__ __constant__ __align__(16) float g_pat[36] = {
    PROW(0), PROW(1), PROW(2), PROW(3), PROW(4), PROW(5)
};

// Horizontal 6-tap filter for 4 adjacent output columns (j = 4t..4t+3).
__device__ __forceinline__ float4 hfilt4(const float* __restrict__ row,
                                         int cA, int cB, int cC, int cD,
                                         bool left, bool right)
{
    float4 A = *reinterpret_cast<const float4*>(row + cA);
    float4 B = *reinterpret_cast<const float4*>(row + cB);
    float4 C = *reinterpret_cast<const float4*>(row + cC);
    float4 D = *reinterpret_cast<const float4*>(row + cD);
    if (left)  { A.z = B.x; A.w = B.x; }   // cols -2,-1 -> col 0
    if (right) { D.x = C.w; D.y = C.w; }   // cols 768,769 -> col 767
    float4 h;
    h.x = fmaf(WN0, A.z, fmaf(WN1, A.w, fmaf(WN2, B.x,
          fmaf(WN2, B.y, fmaf(WN1, B.z, WN0 * B.w)))));
    h.y = fmaf(WN0, B.x, fmaf(WN1, B.y, fmaf(WN2, B.z,
          fmaf(WN2, B.w, fmaf(WN1, C.x, WN0 * C.y)))));
    h.z = fmaf(WN0, B.z, fmaf(WN1, B.w, fmaf(WN2, C.x,
          fmaf(WN2, C.y, fmaf(WN1, C.z, WN0 * C.w)))));
    h.w = fmaf(WN0, C.x, fmaf(WN1, C.y, fmaf(WN2, C.z,
          fmaf(WN2, C.w, fmaf(WN1, D.x, WN0 * D.y)))));
    return h;
}

__device__ __forceinline__ const float* rowptr(const float* base, int r)
{
    r = r < 0 ? 0 : (r > IN_H - 1 ? IN_H - 1 : r);
    return base + r * IN_W;
}

__global__ __launch_bounds__(BLK) void fused_kernel(
    const float* __restrict__ in, float* __restrict__ out)
{
    __shared__ __align__(16) float4 spat[SMEM_F4];
    const int bid = blockIdx.x;
    const int tid = threadIdx.x;

    if (bid >= RES_BLOCKS) {
        // ------------------- fill: TMA bulk stores -------------------
        const int fb = bid - RES_BLOCKS;
        const float4* p4 = reinterpret_cast<const float4*>(g_pat);
        #pragma unroll
        for (int i = tid; i < SMEM_F4; i += BLK)
            spat[i] = p4[i % 9];
        __syncthreads();
        if (tid == 0) {
            asm volatile("fence.proxy.async.shared::cta;" ::: "memory");
            uint32_t saddr = (uint32_t)__cvta_generic_to_shared(spat);
            char* dst = reinterpret_cast<char*>(out + RES_ELEMS)
                      + (size_t)fb * (CHUNK_BYTES * CHUNKS_PER_FILL);
            #pragma unroll
            for (int k = 0; k < CHUNKS_PER_FILL; k++) {
                asm volatile(
                    "cp.async.bulk.global.shared::cta.bulk_group [%0], [%1], %2;"
                    :: "l"(dst + (size_t)k * CHUNK_BYTES), "r"(saddr),
                       "n"(CHUNK_BYTES) : "memory");
            }
            asm volatile("cp.async.bulk.commit_group;" ::: "memory");
            asm volatile("cp.async.bulk.wait_group 0;" ::: "memory");
        }
        return;
    }

    // ------------------- resize -------------------
    const int w     = bid * BLK + tid;
    const int t     = w % TCOLS;
    const int rest  = w / TCOLS;
    const int strip = rest % NSTRIPS;
    const int bc    = rest / NSTRIPS;
    const int i0    = strip * STRIP;

    const float* base = in + (size_t)bc * (IN_H * IN_W);
    float* dst = out + (size_t)bc * (OUT_H * OUT_W) + 4 * t;

    const bool left  = (t == 0);
    const bool right = (t == TCOLS - 1);
    const int cB = 8 * t;
    const int cC = cB + 4;
    const int cA = left  ? 0        : cB - 4;
    const int cD = right ? IN_W - 4 : cB + 8;

    const int r0 = 2 * i0 - 2;
    float4 h0 = hfilt4(rowptr(base, r0 + 0), cA, cB, cC, cD, left, right);
    float4 h1 = hfilt4(rowptr(base, r0 + 1), cA, cB, cC, cD, left, right);
    float4 h2 = hfilt4(rowptr(base, r0 + 2), cA, cB, cC, cD, left, right);
    float4 h3 = hfilt4(rowptr(base, r0 + 3), cA, cB, cC, cD, left, right);
    float4 h4 = hfilt4(rowptr(base, r0 + 4), cA, cB, cC, cD, left, right);
    float4 h5 = hfilt4(rowptr(base, r0 + 5), cA, cB, cC, cD, left, right);

    #pragma unroll
    for (int ii = 0; ii < STRIP; ii++) {
        float4 o;
        o.x = fmaf(WN0, h0.x, fmaf(WN1, h1.x, fmaf(WN2, h2.x,
              fmaf(WN2, h3.x, fmaf(WN1, h4.x, WN0 * h5.x)))));
        o.y = fmaf(WN0, h0.y, fmaf(WN1, h1.y, fmaf(WN2, h2.y,
              fmaf(WN2, h3.y, fmaf(WN1, h4.y, WN0 * h5.y)))));
        o.z = fmaf(WN0, h0.z, fmaf(WN1, h1.z, fmaf(WN2, h2.z,
              fmaf(WN2, h3.z, fmaf(WN1, h4.z, WN0 * h5.z)))));
        o.w = fmaf(WN0, h0.w, fmaf(WN1, h1.w, fmaf(WN2, h2.w,
              fmaf(WN2, h3.w, fmaf(WN1, h4.w, WN0 * h5.w)))));
        *reinterpret_cast<float4*>(dst + (size_t)(i0 + ii) * OUT_W) = o;

        if (ii < STRIP - 1) {
            h0 = h2; h1 = h3; h2 = h4; h3 = h5;
            const int rn = 2 * (i0 + ii + 1) + 2;
            h4 = hfilt4(rowptr(base, rn),     cA, cB, cC, cD, left, right);
            h5 = hfilt4(rowptr(base, rn + 1), cA, cB, cC, cD, left, right);
        }
    }
}

extern "C" void kernel_launch(void* const* d_in, const int* in_sizes, int n_in,
                              void* d_out, int out_size)
{
    const float* in = (const float*)d_in[0];
    float* out = (float*)d_out;
    fused_kernel<<<RES_BLOCKS + FILL_BLOCKS, BLK>>>(in, out);
}

// round 6
// speedup vs baseline: 1.1046x; 1.1046x over previous
#include <cuda_runtime.h>
#include <cstdint>

// ---------------------------------------------------------------------------
// Bicubic downsample 768x768 -> 384x384 (scale exactly 0.5) + constant
// 36-weight pattern tiled into the second output. Single fused launch.
//   wn  = {-9, 29, 111, 111, 29, -9} / 262
//   pat = a_p*a_q / 68644
//   gather rows/cols: clamp(2*o - 2 + tap, 0, 767)
// ---------------------------------------------------------------------------

#define IN_H   768
#define IN_W   768
#define OUT_H  384
#define OUT_W  384
#define BC     12
#define RES_ELEMS (BC * OUT_H * OUT_W)         // 1,769,472
#define N4        (4 * OUT_H * OUT_W * 36 / 4) // 5,308,416 float4s

#define BLK    256
#define TCOLS  96                              // 4 output cols per thread
#define STRIP  8
#define NSTRIPS (OUT_H / STRIP)                // 48
#define RES_THREADS (BC * NSTRIPS * TCOLS)     // 55,296
#define RES_BLOCKS  (RES_THREADS / BLK)        // 216

#define FILL_K      16
#define FILL_T      (N4 / FILL_K)              // 331,776 (multiple of 9)
#define FILL_BLOCKS (FILL_T / BLK)             // 1296

#define WN0 ((float)(-9.0  / 262.0))
#define WN1 ((float)(29.0  / 262.0))
#define WN2 ((float)(111.0 / 262.0))

#define AD(p) ((p)==0 ? -9.0 : (p)==1 ? 29.0 : (p)==2 ? 111.0 : \
               (p)==3 ? 111.0 : (p)==4 ? 29.0 : -9.0)
#define PW(p,q) ((float)(AD(p) * AD(q) / 68644.0))
#define PROW(p) PW(p,0), PW(p,1), PW(p,2), PW(p,3), PW(p,4), PW(p,5)

__device__ __constant__ __align__(16) float g_pat[36] = {
    PROW(0), PROW(1), PROW(2), PROW(3), PROW(4), PROW(5)
};

// Horizontal 6-tap filter for 4 adjacent output columns (j = 4t..4t+3).
__device__ __forceinline__ float4 hfilt4(const float* __restrict__ row,
                                         int cA, int cB, int cC, int cD,
                                         bool left, bool right)
{
    float4 A = *reinterpret_cast<const float4*>(row + cA);
    float4 B = *reinterpret_cast<const float4*>(row + cB);
    float4 C = *reinterpret_cast<const float4*>(row + cC);
    float4 D = *reinterpret_cast<const float4*>(row + cD);
    if (left)  { A.z = B.x; A.w = B.x; }   // cols -2,-1 -> col 0
    if (right) { D.x = C.w; D.y = C.w; }   // cols 768,769 -> col 767
    float4 h;
    h.x = fmaf(WN0, A.z, fmaf(WN1, A.w, fmaf(WN2, B.x,
          fmaf(WN2, B.y, fmaf(WN1, B.z, WN0 * B.w)))));
    h.y = fmaf(WN0, B.x, fmaf(WN1, B.y, fmaf(WN2, B.z,
          fmaf(WN2, B.w, fmaf(WN1, C.x, WN0 * C.y)))));
    h.z = fmaf(WN0, B.z, fmaf(WN1, B.w, fmaf(WN2, C.x,
          fmaf(WN2, C.y, fmaf(WN1, C.z, WN0 * C.w)))));
    h.w = fmaf(WN0, C.x, fmaf(WN1, C.y, fmaf(WN2, C.z,
          fmaf(WN2, C.w, fmaf(WN1, D.x, WN0 * D.y)))));
    return h;
}

__device__ __forceinline__ const float* rowptr(const float* base, int r)
{
    r = r < 0 ? 0 : (r > IN_H - 1 ? IN_H - 1 : r);
    return base + r * IN_W;
}

__global__ __launch_bounds__(BLK) void fused_kernel(
    const float* __restrict__ in, float* __restrict__ out)
{
    __shared__ __align__(16) float4 spat[9];   // 144 B: one pattern period
    const int bid = blockIdx.x;
    const int tid = threadIdx.x;

    if (bid >= RES_BLOCKS) {
        // --------- fill: 16 coalesced STG.128 per thread ---------
        if (tid < 9)
            spat[tid] = reinterpret_cast<const float4*>(g_pat)[tid];
        __syncthreads();
        const int t = (bid - RES_BLOCKS) * BLK + tid;  // 0..FILL_T-1
        const float4 v = spat[t % 9];
        float4* __restrict__ dst = reinterpret_cast<float4*>(out + RES_ELEMS);
        #pragma unroll
        for (int k = 0; k < FILL_K; k++)
            dst[t + k * FILL_T] = v;                   // stride % 9 == 0
        return;
    }

    // ------------------- resize -------------------
    const int w     = bid * BLK + tid;
    const int t     = w % TCOLS;
    const int rest  = w / TCOLS;
    const int strip = rest % NSTRIPS;
    const int bc    = rest / NSTRIPS;
    const int i0    = strip * STRIP;

    const float* base = in + (size_t)bc * (IN_H * IN_W);
    float* dst = out + (size_t)bc * (OUT_H * OUT_W) + 4 * t;

    const bool left  = (t == 0);
    const bool right = (t == TCOLS - 1);
    const int cB = 8 * t;
    const int cC = cB + 4;
    const int cA = left  ? 0        : cB - 4;
    const int cD = right ? IN_W - 4 : cB + 8;

    const int r0 = 2 * i0 - 2;
    float4 h0 = hfilt4(rowptr(base, r0 + 0), cA, cB, cC, cD, left, right);
    float4 h1 = hfilt4(rowptr(base, r0 + 1), cA, cB, cC, cD, left, right);
    float4 h2 = hfilt4(rowptr(base, r0 + 2), cA, cB, cC, cD, left, right);
    float4 h3 = hfilt4(rowptr(base, r0 + 3), cA, cB, cC, cD, left, right);
    float4 h4 = hfilt4(rowptr(base, r0 + 4), cA, cB, cC, cD, left, right);
    float4 h5 = hfilt4(rowptr(base, r0 + 5), cA, cB, cC, cD, left, right);

    #pragma unroll
    for (int ii = 0; ii < STRIP; ii++) {
        float4 o;
        o.x = fmaf(WN0, h0.x, fmaf(WN1, h1.x, fmaf(WN2, h2.x,
              fmaf(WN2, h3.x, fmaf(WN1, h4.x, WN0 * h5.x)))));
        o.y = fmaf(WN0, h0.y, fmaf(WN1, h1.y, fmaf(WN2, h2.y,
              fmaf(WN2, h3.y, fmaf(WN1, h4.y, WN0 * h5.y)))));
        o.z = fmaf(WN0, h0.z, fmaf(WN1, h1.z, fmaf(WN2, h2.z,
              fmaf(WN2, h3.z, fmaf(WN1, h4.z, WN0 * h5.z)))));
        o.w = fmaf(WN0, h0.w, fmaf(WN1, h1.w, fmaf(WN2, h2.w,
              fmaf(WN2, h3.w, fmaf(WN1, h4.w, WN0 * h5.w)))));
        *reinterpret_cast<float4*>(dst + (size_t)(i0 + ii) * OUT_W) = o;

        if (ii < STRIP - 1) {
            h0 = h2; h1 = h3; h2 = h4; h3 = h5;
            const int rn = 2 * (i0 + ii + 1) + 2;
            h4 = hfilt4(rowptr(base, rn),     cA, cB, cC, cD, left, right);
            h5 = hfilt4(rowptr(base, rn + 1), cA, cB, cC, cD, left, right);
        }
    }
}

extern "C" void kernel_launch(void* const* d_in, const int* in_sizes, int n_in,
                              void* d_out, int out_size)
{
    const float* in = (const float*)d_in[0];
    float* out = (float*)d_out;
    fused_kernel<<<RES_BLOCKS + FILL_BLOCKS, BLK>>>(in, out);
}

// round 7
// speedup vs baseline: 1.5550x; 1.4078x over previous
#include <cuda_runtime.h>
#include <cstdint>

// ---------------------------------------------------------------------------
// Bicubic downsample 768x768 -> 384x384 (scale exactly 0.5) + constant
// 36-weight pattern tiled into the second output. Single fused launch.
//   wn  = {-9, 29, 111, 111, 29, -9} / 262
//   pat = a_p*a_q / 68644
//   gather rows/cols: clamp(2*o - 2 + tap, 0, 767)
// ---------------------------------------------------------------------------

#define IN_H   768
#define IN_W   768
#define OUT_H  384
#define OUT_W  384
#define BC     12
#define RES_ELEMS (BC * OUT_H * OUT_W)         // 1,769,472
#define N4        (4 * OUT_H * OUT_W * 36 / 4) // 5,308,416 float4s

#define BLK    256
#define TCOLS  96                              // 4 output cols per thread
#define STRIP  8
#define NSTRIPS (OUT_H / STRIP)                // 48
#define RES_THREADS (BC * NSTRIPS * TCOLS)     // 55,296
#define RES_BLOCKS  (RES_THREADS / BLK)        // 216

#define FILL_K      16
#define FILL_T      (N4 / FILL_K)              // 331,776 (multiple of 9)
#define FILL_BLOCKS (FILL_T / BLK)             // 1296

#define WN0 ((float)(-9.0  / 262.0))
#define WN1 ((float)(29.0  / 262.0))
#define WN2 ((float)(111.0 / 262.0))

#define AD(p) ((p)==0 ? -9.0 : (p)==1 ? 29.0 : (p)==2 ? 111.0 : \
               (p)==3 ? 111.0 : (p)==4 ? 29.0 : -9.0)
#define PW(p,q) ((float)(AD(p) * AD(q) / 68644.0))
#define PROW(p) PW(p,0), PW(p,1), PW(p,2), PW(p,3), PW(p,4), PW(p,5)

__device__ __constant__ __align__(16) float g_pat[36] = {
    PROW(0), PROW(1), PROW(2), PROW(3), PROW(4), PROW(5)
};

// Horizontal 6-tap filter for 4 adjacent output columns (j = 4t..4t+3).
__device__ __forceinline__ float4 hfilt4(const float* __restrict__ row,
                                         int cA, int cB, int cC, int cD,
                                         bool left, bool right)
{
    float4 A = *reinterpret_cast<const float4*>(row + cA);
    float4 B = *reinterpret_cast<const float4*>(row + cB);
    float4 C = *reinterpret_cast<const float4*>(row + cC);
    float4 D = *reinterpret_cast<const float4*>(row + cD);
    if (left)  { A.z = B.x; A.w = B.x; }   // cols -2,-1 -> col 0
    if (right) { D.x = C.w; D.y = C.w; }   // cols 768,769 -> col 767
    float4 h;
    h.x = fmaf(WN0, A.z, fmaf(WN1, A.w, fmaf(WN2, B.x,
          fmaf(WN2, B.y, fmaf(WN1, B.z, WN0 * B.w)))));
    h.y = fmaf(WN0, B.x, fmaf(WN1, B.y, fmaf(WN2, B.z,
          fmaf(WN2, B.w, fmaf(WN1, C.x, WN0 * C.y)))));
    h.z = fmaf(WN0, B.z, fmaf(WN1, B.w, fmaf(WN2, C.x,
          fmaf(WN2, C.y, fmaf(WN1, C.z, WN0 * C.w)))));
    h.w = fmaf(WN0, C.x, fmaf(WN1, C.y, fmaf(WN2, C.z,
          fmaf(WN2, C.w, fmaf(WN1, D.x, WN0 * D.y)))));
    return h;
}

__device__ __forceinline__ const float* rowptr(const float* base, int r)
{
    r = r < 0 ? 0 : (r > IN_H - 1 ? IN_H - 1 : r);
    return base + r * IN_W;
}

__global__ __launch_bounds__(BLK, 4) void fused_kernel(
    const float* __restrict__ in, float* __restrict__ out)
{
    __shared__ __align__(16) float4 spat[9];   // 144 B: one pattern period
    const int bid = blockIdx.x;
    const int tid = threadIdx.x;

    if (bid >= RES_BLOCKS) {
        // --- fill: 16 coalesced streaming STG.128 per thread ---
        if (tid < 9)
            spat[tid] = reinterpret_cast<const float4*>(g_pat)[tid];
        __syncthreads();
        const int t = (bid - RES_BLOCKS) * BLK + tid;  // 0..FILL_T-1
        const float4 v = spat[t % 9];
        float4* __restrict__ dst = reinterpret_cast<float4*>(out + RES_ELEMS);
        #pragma unroll
        for (int k = 0; k < FILL_K; k++)
            __stcs(dst + t + k * FILL_T, v);           // stride % 9 == 0
        return;
    }

    // ------------------- resize -------------------
    const int w     = bid * BLK + tid;
    const int t     = w % TCOLS;
    const int rest  = w / TCOLS;
    const int strip = rest % NSTRIPS;
    const int bc    = rest / NSTRIPS;
    const int i0    = strip * STRIP;

    const float* base = in + (size_t)bc * (IN_H * IN_W);
    float* dst = out + (size_t)bc * (OUT_H * OUT_W) + 4 * t;

    const bool left  = (t == 0);
    const bool right = (t == TCOLS - 1);
    const int cB = 8 * t;
    const int cC = cB + 4;
    const int cA = left  ? 0        : cB - 4;
    const int cD = right ? IN_W - 4 : cB + 8;

    const int r0 = 2 * i0 - 2;
    float4 h0 = hfilt4(rowptr(base, r0 + 0), cA, cB, cC, cD, left, right);
    float4 h1 = hfilt4(rowptr(base, r0 + 1), cA, cB, cC, cD, left, right);
    float4 h2 = hfilt4(rowptr(base, r0 + 2), cA, cB, cC, cD, left, right);
    float4 h3 = hfilt4(rowptr(base, r0 + 3), cA, cB, cC, cD, left, right);
    float4 h4 = hfilt4(rowptr(base, r0 + 4), cA, cB, cC, cD, left, right);
    float4 h5 = hfilt4(rowptr(base, r0 + 5), cA, cB, cC, cD, left, right);

    #pragma unroll
    for (int ii = 0; ii < STRIP; ii++) {
        float4 o;
        o.x = fmaf(WN0, h0.x, fmaf(WN1, h1.x, fmaf(WN2, h2.x,
              fmaf(WN2, h3.x, fmaf(WN1, h4.x, WN0 * h5.x)))));
        o.y = fmaf(WN0, h0.y, fmaf(WN1, h1.y, fmaf(WN2, h2.y,
              fmaf(WN2, h3.y, fmaf(WN1, h4.y, WN0 * h5.y)))));
        o.z = fmaf(WN0, h0.z, fmaf(WN1, h1.z, fmaf(WN2, h2.z,
              fmaf(WN2, h3.z, fmaf(WN1, h4.z, WN0 * h5.z)))));
        o.w = fmaf(WN0, h0.w, fmaf(WN1, h1.w, fmaf(WN2, h2.w,
              fmaf(WN2, h3.w, fmaf(WN1, h4.w, WN0 * h5.w)))));
        __stcs(reinterpret_cast<float4*>(dst + (size_t)(i0 + ii) * OUT_W), o);

        if (ii < STRIP - 1) {
            h0 = h2; h1 = h3; h2 = h4; h3 = h5;
            const int rn = 2 * (i0 + ii + 1) + 2;
            h4 = hfilt4(rowptr(base, rn),     cA, cB, cC, cD, left, right);
            h5 = hfilt4(rowptr(base, rn + 1), cA, cB, cC, cD, left, right);
        }
    }
}

extern "C" void kernel_launch(void* const* d_in, const int* in_sizes, int n_in,
                              void* d_out, int out_size)
{
    const float* in = (const float*)d_in[0];
    float* out = (float*)d_out;
    fused_kernel<<<RES_BLOCKS + FILL_BLOCKS, BLK>>>(in, out);
}